// round 13
// baseline (speedup 1.0000x reference)
#include <cuda_runtime.h>

// ---------------------------------------------------------------------------
// NodeLevelEncoder: 3x GCN + mean pool + 2x degenerate LSTM + projection.
// R13: GEMM moved to tensor cores via tf32 mma.sync with 3xTF32 compensation
//      (hi/lo split => ~fp32 accuracy). Agg-before-transform retained.
// ---------------------------------------------------------------------------

#define MAXN 100000
#define MAXE 800000
#define MAXG 64

__device__ __align__(16) float g_bufA[(size_t)MAXN * 512]; // activations (GEMM out)
__device__ __align__(16) float g_bufB[(size_t)MAXN * 256]; // aggregated (GEMM in)
__device__ float g_dinv[MAXN];
__device__ int   g_icnt[MAXN];
__device__ int   g_off[MAXN];
__device__ int   g_cur[MAXN];
__device__ int   g_psrc[MAXE];
__device__ float g_pw[MAXE];
__device__ int   g_bnd[MAXG + 1];
__device__ __align__(16) float g_pooled[MAXG * 512];
__device__ __align__(16) float g_gates[MAXG * 1024];
__device__ __align__(16) float g_hl[MAXG * 256];
__device__ int   g_w64;
__device__ int   g_b64;

static inline int cdiv(int a, int b) { return (a + b - 1) / b; }

// ---------------------------------------------------------------------------
// dtype detection: int64 (LE) data has zero high-words in odd int32 slots.
__global__ void k_detect(const int* ei32, int eslots, const int* b32, int bslots) {
    int w64 = 1;
    for (int k = 0; k < 64; k++) {
        long long j = ((long long)(2 * k + 1) * eslots) / 128;
        int idx = (int)(j | 1);
        if (idx < eslots && ei32[idx] != 0) { w64 = 0; break; }
    }
    g_w64 = w64;
    int b64 = 1;
    for (int k = 0; k < 64; k++) {
        long long j = ((long long)(2 * k + 1) * bslots) / 128;
        int idx = (int)(j | 1);
        if (idx < bslots && b32[idx] != 0) { b64 = 0; break; }
    }
    g_b64 = b64;
}

__device__ __forceinline__ int load_idx(const void* p, long long i, int is64) {
    return is64 ? (int)((const long long*)p)[i] : ((const int*)p)[i];
}

// ---------------------------------------------------------------------------
__global__ void k_zero_cnt(int N) {
    int i = blockIdx.x * blockDim.x + threadIdx.x;
    if (i < N) { g_icnt[i] = 0; g_cur[i] = 0; }
}

__global__ void k_count(const void* __restrict__ ei, int E, int N) {
    int e = blockIdx.x * blockDim.x + threadIdx.x;
    if (e >= E) return;
    int d = load_idx(ei, (long long)E + e, g_w64);
    if ((unsigned)d < (unsigned)N) atomicAdd(&g_icnt[d], 1);
}

__global__ void k_dinv(int N) {
    int i = blockIdx.x * blockDim.x + threadIdx.x;
    if (i < N) g_dinv[i] = rsqrtf((float)g_icnt[i] + 1.0f);
}

__global__ __launch_bounds__(1024) void k_scan(int N) {
    __shared__ int ssum[1024];
    int tid = threadIdx.x;
    int chunk = (N + 1023) >> 10;
    int a0 = tid * chunk;
    int a1 = min(a0 + chunk, N);
    int s = 0;
    for (int i = a0; i < a1; i++) s += g_icnt[i];
    ssum[tid] = s;
    __syncthreads();
    for (int d = 1; d < 1024; d <<= 1) {
        int v = (tid >= d) ? ssum[tid - d] : 0;
        __syncthreads();
        ssum[tid] += v;
        __syncthreads();
    }
    int run = (tid == 0) ? 0 : ssum[tid - 1];
    for (int i = a0; i < a1; i++) { g_off[i] = run; run += g_icnt[i]; }
}

__global__ void k_place(const void* __restrict__ ei, int E, int N) {
    int e = blockIdx.x * blockDim.x + threadIdx.x;
    if (e >= E) return;
    int w64 = g_w64;
    int s = load_idx(ei, e, w64);
    int d = load_idx(ei, (long long)E + e, w64);
    if ((unsigned)s >= (unsigned)N || (unsigned)d >= (unsigned)N) return;
    int p = atomicAdd(&g_cur[d], 1);
    int o = g_off[d] + p;
    g_psrc[o] = s;
    g_pw[o] = g_dinv[s] * g_dinv[d];
}

__global__ void k_bounds(const void* __restrict__ batch, int N, int G) {
    int g = threadIdx.x;
    if (g > G) return;
    if (g == G) { g_bnd[G] = N; return; }
    int b64 = g_b64;
    int lo = 0, hi = N;
    while (lo < hi) {
        int mid = (lo + hi) >> 1;
        if (load_idx(batch, mid, b64) < g) lo = mid + 1; else hi = mid;
    }
    g_bnd[g] = lo;
}

// ---------------------------------------------------------------------------
// GCN aggregation in INPUT dim (pure gather, before transform).
// ---------------------------------------------------------------------------
__global__ void k_agg(int a_sel, const float* __restrict__ ext, int total, int sh) {
    int i = blockIdx.x * blockDim.x + threadIdx.x;
    if (i >= total) return;
    int n = i >> sh;
    int c = i & ((1 << sh) - 1);

    const float4* act = a_sel ? (const float4*)g_bufA : (const float4*)ext;
    float4* out = (float4*)g_bufB;

    float s = g_dinv[n];
    s *= s;
    float4 t = act[i];
    float4 acc = make_float4(t.x * s, t.y * s, t.z * s, t.w * s);

    int e0 = g_off[n];
    int e1 = e0 + g_icnt[n];
    for (int e = e0; e < e1; e++) {
        int sn = g_psrc[e];
        float w = g_pw[e];
        float4 v = act[((size_t)sn << sh) + c];
        acc.x += v.x * w; acc.y += v.y * w; acc.z += v.z * w; acc.w += v.w * w;
    }
    out[i] = acc;
}

// ---------------------------------------------------------------------------
// tf32 tensor-core GEMM with 3xTF32 compensation + fused bias/relu epilogue.
//   g_bufA[N,C] = relu(g_bufB[N,K] @ W[K,C] + bias)
// BM=BN=128, BK=16. 256 threads = 8 warps in 2(m) x 4(n); warp tile 64x32 =
// 4x4 mma tiles of m16n8k8. K % 16 == 0 (32/128/256), C % 128 == 0.
// ---------------------------------------------------------------------------
__device__ __forceinline__ unsigned f2tf(float x) {
    unsigned r;
    asm("cvt.rna.tf32.f32 %0, %1;" : "=r"(r) : "f"(x));
    return r;
}

__device__ __forceinline__ void mma8(float c[4], unsigned a0, unsigned a1,
                                     unsigned a2, unsigned a3,
                                     unsigned b0, unsigned b1) {
    asm("mma.sync.aligned.m16n8k8.row.col.f32.tf32.tf32.f32 "
        "{%0,%1,%2,%3},{%4,%5,%6,%7},{%8,%9},{%0,%1,%2,%3};"
        : "+f"(c[0]), "+f"(c[1]), "+f"(c[2]), "+f"(c[3])
        : "r"(a0), "r"(a1), "r"(a2), "r"(a3), "r"(b0), "r"(b1));
}

__global__ __launch_bounds__(256, 1) void k_gemm_tf32(const float* __restrict__ W,
                                                      const float* __restrict__ bias,
                                                      int Nrows, int K, int C) {
    __shared__ __align__(16) float As[128][20];   // [m][k0..15] + pad4 (conflict-free frags)
    __shared__ __align__(16) float Bs[16][132];   // [k][n0..127] + pad4

    const float* A = g_bufB;
    float* const out = g_bufA;

    int tid = threadIdx.x;
    int wid = tid >> 5, lane = tid & 31;
    int gid = lane >> 2, tig = lane & 3;
    int wm = wid & 1, wn = wid >> 1;              // 2 x 4 warp grid
    int row0 = blockIdx.y * 128, col0 = blockIdx.x * 128;
    int mbase = wm * 64, nbase = wn * 32;

    float acc[4][4][4];
#pragma unroll
    for (int mt = 0; mt < 4; mt++)
#pragma unroll
        for (int nt = 0; nt < 4; nt++)
#pragma unroll
            for (int r = 0; r < 4; r++) acc[mt][nt][r] = 0.f;

    int ar = tid >> 1;            // A tile row 0..127
    int ak = (tid & 1) * 8;       // 0 or 8
    int bk = tid >> 4;            // 0..15
    int bc = (tid & 15) * 8;      // 0..120

    for (int kt = 0; kt < K; kt += 16) {
        int grow = row0 + ar;
        float4 av0 = make_float4(0.f, 0.f, 0.f, 0.f);
        float4 av1 = av0;
        if (grow < Nrows) {
            const float* ap = &A[(size_t)grow * K + kt + ak];
            av0 = *(const float4*)ap;
            av1 = *(const float4*)(ap + 4);
        }
        *(float4*)&As[ar][ak] = av0;
        *(float4*)&As[ar][ak + 4] = av1;

        const float* bp = &W[(size_t)(kt + bk) * C + col0 + bc];
        *(float4*)&Bs[bk][bc] = *(const float4*)bp;
        *(float4*)&Bs[bk][bc + 4] = *(const float4*)(bp + 4);
        __syncthreads();

#pragma unroll
        for (int ks = 0; ks < 2; ks++) {
            int kb = ks * 8;
            unsigned ahi[4][4], alo[4][4];
#pragma unroll
            for (int mt = 0; mt < 4; mt++) {
                int m = mbase + mt * 16 + gid;
                float a0 = As[m][kb + tig];
                float a1 = As[m + 8][kb + tig];
                float a2 = As[m][kb + tig + 4];
                float a3 = As[m + 8][kb + tig + 4];
                ahi[mt][0] = f2tf(a0); alo[mt][0] = f2tf(a0 - __uint_as_float(ahi[mt][0]));
                ahi[mt][1] = f2tf(a1); alo[mt][1] = f2tf(a1 - __uint_as_float(ahi[mt][1]));
                ahi[mt][2] = f2tf(a2); alo[mt][2] = f2tf(a2 - __uint_as_float(ahi[mt][2]));
                ahi[mt][3] = f2tf(a3); alo[mt][3] = f2tf(a3 - __uint_as_float(ahi[mt][3]));
            }
            unsigned bhi[4][2], blo[4][2];
#pragma unroll
            for (int nt = 0; nt < 4; nt++) {
                int n = nbase + nt * 8 + gid;
                float b0 = Bs[kb + tig][n];
                float b1 = Bs[kb + tig + 4][n];
                bhi[nt][0] = f2tf(b0); blo[nt][0] = f2tf(b0 - __uint_as_float(bhi[nt][0]));
                bhi[nt][1] = f2tf(b1); blo[nt][1] = f2tf(b1 - __uint_as_float(bhi[nt][1]));
            }
#pragma unroll
            for (int mt = 0; mt < 4; mt++)
#pragma unroll
                for (int nt = 0; nt < 4; nt++) {
                    mma8(acc[mt][nt], ahi[mt][0], ahi[mt][1], ahi[mt][2], ahi[mt][3],
                         bhi[nt][0], bhi[nt][1]);
                    mma8(acc[mt][nt], ahi[mt][0], ahi[mt][1], ahi[mt][2], ahi[mt][3],
                         blo[nt][0], blo[nt][1]);
                    mma8(acc[mt][nt], alo[mt][0], alo[mt][1], alo[mt][2], alo[mt][3],
                         bhi[nt][0], bhi[nt][1]);
                }
        }
        __syncthreads();
    }

    // epilogue: bias + relu, write float2 per (row, mma-tile)
#pragma unroll
    for (int mt = 0; mt < 4; mt++) {
#pragma unroll
        for (int nt = 0; nt < 4; nt++) {
            int col = col0 + nbase + nt * 8 + tig * 2;
            float bx = bias[col], by = bias[col + 1];
            int r0 = row0 + mbase + mt * 16 + gid;
            if (r0 < Nrows) {
                float2 o;
                o.x = fmaxf(acc[mt][nt][0] + bx, 0.f);
                o.y = fmaxf(acc[mt][nt][1] + by, 0.f);
                *(float2*)&out[(size_t)r0 * C + col] = o;
            }
            int r1 = r0 + 8;
            if (r1 < Nrows) {
                float2 o;
                o.x = fmaxf(acc[mt][nt][2] + bx, 0.f);
                o.y = fmaxf(acc[mt][nt][3] + by, 0.f);
                *(float2*)&out[(size_t)r1 * C + col] = o;
            }
        }
    }
}

// ---------------------------------------------------------------------------
// mean pool over g_bufA (final activations, 512 ch). No atomics.
// ---------------------------------------------------------------------------
__global__ __launch_bounds__(128) void k_pool() {
    int g = blockIdx.x;
    int c = blockIdx.y * 128 + threadIdx.x;
    int n0 = g_bnd[g];
    int n1 = g_bnd[g + 1];
    float acc = 0.f;
    for (int n = n0; n < n1; n++) acc += g_bufA[(size_t)n * 512 + c];
    float cntf = (float)(n1 - n0);
    g_pooled[g * 512 + c] = acc / fmaxf(cntf, 1.f);
}

// ---------------------------------------------------------------------------
__global__ __launch_bounds__(256) void k_dense(int in_sel,
                                               const float* __restrict__ W,
                                               const float* __restrict__ ba,
                                               const float* __restrict__ bb,
                                               float* out_ext, int In, int Out) {
    __shared__ __align__(16) float sin[512];
    const float* in = in_sel ? g_hl : g_pooled;
    float* out = out_ext ? out_ext : g_gates;
    int g = blockIdx.y;
    for (int k = threadIdx.x; k < In; k += blockDim.x) sin[k] = in[(size_t)g * In + k];
    __syncthreads();
    int j = blockIdx.x * blockDim.x + threadIdx.x;
    if (j >= Out) return;
    float acc = ba[j] + (bb ? bb[j] : 0.f);
    const float4* Wr = (const float4*)(W + (size_t)j * In);
    const float4* xs = (const float4*)sin;
    int k4 = In >> 2;
    for (int k = 0; k < k4; k++) {
        float4 w = Wr[k];
        float4 x = xs[k];
        acc += w.x * x.x + w.y * x.y + w.z * x.z + w.w * x.w;
    }
    out[(size_t)g * Out + j] = acc;
}

// h0=c0=0:  h = sigmoid(o) * tanh( sigmoid(i) * tanh(g) )
__global__ void k_lstm(int total, int H) {
    int i = blockIdx.x * blockDim.x + threadIdx.x;
    if (i >= total) return;
    int g = i / H;
    int j = i - g * H;
    const float* gr = g_gates + (size_t)g * 4 * H;
    float ii = gr[j];
    float gg = gr[2 * H + j];
    float oo = gr[3 * H + j];
    float si = 1.f / (1.f + expf(-ii));
    float so = 1.f / (1.f + expf(-oo));
    float c = si * tanhf(gg);
    g_hl[i] = so * tanhf(c);
}

// ---------------------------------------------------------------------------
extern "C" void kernel_launch(void* const* d_in, const int* in_sizes, int n_in,
                              void* d_out, int out_size) {
    const float* x     = (const float*)d_in[0];
    const void*  ei    = d_in[1];
    const void*  batch = d_in[2];
    const float *W1 = (const float*)d_in[3],  *b1 = (const float*)d_in[4];
    const float *W2 = (const float*)d_in[5],  *b2 = (const float*)d_in[6];
    const float *W3 = (const float*)d_in[7],  *b3 = (const float*)d_in[8];
    const float *Wih0 = (const float*)d_in[9];
    const float *bih0 = (const float*)d_in[11], *bhh0 = (const float*)d_in[12];
    const float *Wih1 = (const float*)d_in[13];
    const float *bih1 = (const float*)d_in[15], *bhh1 = (const float*)d_in[16];
    const float *Wp = (const float*)d_in[17],  *bp = (const float*)d_in[18];
    // Whh0 (d_in[10]) / Whh1 (d_in[14]) are dead: h0 = 0.

    int N = in_sizes[0] / 32;
    int E = in_sizes[1] / 2;
    int G = out_size / 512;

    const int T = 256;

    // ---- dtype detection + CSR + normalization setup ----
    k_detect<<<1, 1>>>((const int*)ei, in_sizes[1], (const int*)batch, in_sizes[2]);
    k_zero_cnt<<<cdiv(N, T), T>>>(N);
    k_count<<<cdiv(E, T), T>>>(ei, E, N);
    k_dinv<<<cdiv(N, T), T>>>(N);
    k_scan<<<1, 1024>>>(N);
    k_place<<<cdiv(E, T), T>>>(ei, E, N);
    k_bounds<<<1, G + 1>>>(batch, N, G);

    // ---- GCN layer 1: agg(x)[N,32] -> relu(@W1+b1)[N,128] ----
    k_agg<<<cdiv(N * 8, T), T>>>(0, x, N * 8, 3);
    k_gemm_tf32<<<dim3(1, cdiv(N, 128)), 256>>>(W1, b1, N, 32, 128);

    // ---- GCN layer 2: agg[N,128] -> relu(@W2+b2)[N,256] ----
    k_agg<<<cdiv(N * 32, T), T>>>(1, nullptr, N * 32, 5);
    k_gemm_tf32<<<dim3(2, cdiv(N, 128)), 256>>>(W2, b2, N, 128, 256);

    // ---- GCN layer 3: agg[N,256] -> relu(@W3+b3)[N,512] ----
    k_agg<<<cdiv(N * 64, T), T>>>(1, nullptr, N * 64, 6);
    k_gemm_tf32<<<dim3(4, cdiv(N, 128)), 256>>>(W3, b3, N, 256, 512);

    // ---- mean pool per graph ----
    k_pool<<<dim3(G, 4), 128>>>();

    // ---- LSTM (degenerate) + projection ----
    k_dense<<<dim3(4, G), 256>>>(0, Wih0, bih0, bhh0, nullptr, 512, 1024);
    k_lstm<<<cdiv(G * 256, T), T>>>(G * 256, 256);
    k_dense<<<dim3(4, G), 256>>>(1, Wih1, bih1, bhh1, nullptr, 256, 1024);
    k_lstm<<<cdiv(G * 256, T), T>>>(G * 256, 256);
    k_dense<<<dim3(2, G), 256>>>(1, Wp, bp, nullptr, (float*)d_out, 256, 512);
}

// round 14
// speedup vs baseline: 1.1078x; 1.1078x over previous
#include <cuda_runtime.h>

// ---------------------------------------------------------------------------
// NodeLevelEncoder: 3x GCN + mean pool + 2x degenerate LSTM + projection.
// R14: R12 structure (agg-before-transform + 128x128x8 fused GEMM), with the
// GEMM inner product upgraded to packed fp32 FFMA2 (fma.rn.f32x2) — 2 fp32
// FMAs per issue slot, exact fp32 results. Setup kernels fused 6 -> 4.
// ---------------------------------------------------------------------------

#define MAXN 100000
#define MAXE 800000
#define MAXG 64

__device__ __align__(16) float g_bufA[(size_t)MAXN * 512]; // activations (GEMM out)
__device__ __align__(16) float g_bufB[(size_t)MAXN * 256]; // aggregated (GEMM in)
__device__ float g_dinv[MAXN];
__device__ int   g_icnt[MAXN];
__device__ int   g_off[MAXN];
__device__ int   g_cur[MAXN];
__device__ int   g_psrc[MAXE];
__device__ float g_pw[MAXE];
__device__ int   g_bnd[MAXG + 1];
__device__ __align__(16) float g_pooled[MAXG * 512];
__device__ __align__(16) float g_gates[MAXG * 1024];
__device__ __align__(16) float g_hl[MAXG * 256];
__device__ int   g_w64;
__device__ int   g_b64;

static inline int cdiv(int a, int b) { return (a + b - 1) / b; }

// ---------------------------------------------------------------------------
// fused: zero counters + dtype detection (int64 LE data has zero high-words
// in odd int32 slots; int32 data doesn't, across 64 spread samples).
__global__ void k_detect_zero(const int* ei32, int eslots, const int* b32,
                              int bslots, int N) {
    int i = blockIdx.x * blockDim.x + threadIdx.x;
    if (i < N) { g_icnt[i] = 0; g_cur[i] = 0; }
    if (blockIdx.x == 0 && threadIdx.x == 0) {
        int w64 = 1;
        for (int k = 0; k < 64; k++) {
            long long j = ((long long)(2 * k + 1) * eslots) / 128;
            int idx = (int)(j | 1);
            if (idx < eslots && ei32[idx] != 0) { w64 = 0; break; }
        }
        g_w64 = w64;
        int b64 = 1;
        for (int k = 0; k < 64; k++) {
            long long j = ((long long)(2 * k + 1) * bslots) / 128;
            int idx = (int)(j | 1);
            if (idx < bslots && b32[idx] != 0) { b64 = 0; break; }
        }
        g_b64 = b64;
    }
}

__device__ __forceinline__ int load_idx(const void* p, long long i, int is64) {
    return is64 ? (int)((const long long*)p)[i] : ((const int*)p)[i];
}

__global__ void k_count(const void* __restrict__ ei, int E, int N) {
    int e = blockIdx.x * blockDim.x + threadIdx.x;
    if (e >= E) return;
    int d = load_idx(ei, (long long)E + e, g_w64);
    if ((unsigned)d < (unsigned)N) atomicAdd(&g_icnt[d], 1);
}

// fused: dinv + exclusive scan (icnt -> off) + per-graph bounds. 1 block.
__global__ __launch_bounds__(1024) void k_prep(const void* __restrict__ batch,
                                               int N, int G) {
    __shared__ int ssum[1024];
    int tid = threadIdx.x;
    int chunk = (N + 1023) >> 10;
    int a0 = tid * chunk;
    int a1 = min(a0 + chunk, N);
    int s = 0;
    for (int i = a0; i < a1; i++) {
        int c = g_icnt[i];
        g_dinv[i] = rsqrtf((float)c + 1.0f);
        s += c;
    }
    ssum[tid] = s;
    __syncthreads();
    for (int d = 1; d < 1024; d <<= 1) {
        int v = (tid >= d) ? ssum[tid - d] : 0;
        __syncthreads();
        ssum[tid] += v;
        __syncthreads();
    }
    int run = (tid == 0) ? 0 : ssum[tid - 1];
    for (int i = a0; i < a1; i++) { g_off[i] = run; run += g_icnt[i]; }

    // bounds over SORTED batch_idx
    if (tid <= G) {
        if (tid == G) g_bnd[G] = N;
        else {
            int b64 = g_b64;
            int lo = 0, hi = N;
            while (lo < hi) {
                int mid = (lo + hi) >> 1;
                if (load_idx(batch, mid, b64) < tid) lo = mid + 1; else hi = mid;
            }
            g_bnd[tid] = lo;
        }
    }
}

__global__ void k_place(const void* __restrict__ ei, int E, int N) {
    int e = blockIdx.x * blockDim.x + threadIdx.x;
    if (e >= E) return;
    int w64 = g_w64;
    int s = load_idx(ei, e, w64);
    int d = load_idx(ei, (long long)E + e, w64);
    if ((unsigned)s >= (unsigned)N || (unsigned)d >= (unsigned)N) return;
    int p = atomicAdd(&g_cur[d], 1);
    int o = g_off[d] + p;
    g_psrc[o] = s;
    g_pw[o] = g_dinv[s] * g_dinv[d];
}

// ---------------------------------------------------------------------------
// GCN aggregation in INPUT dim (pure gather, before transform).
// ---------------------------------------------------------------------------
__global__ void k_agg(int a_sel, const float* __restrict__ ext, int total, int sh) {
    int i = blockIdx.x * blockDim.x + threadIdx.x;
    if (i >= total) return;
    int n = i >> sh;
    int c = i & ((1 << sh) - 1);

    const float4* act = a_sel ? (const float4*)g_bufA : (const float4*)ext;
    float4* out = (float4*)g_bufB;

    float s = g_dinv[n];
    s *= s;
    float4 t = act[i];
    float4 acc = make_float4(t.x * s, t.y * s, t.z * s, t.w * s);

    int e0 = g_off[n];
    int e1 = e0 + g_icnt[n];
    for (int e = e0; e < e1; e++) {
        int sn = g_psrc[e];
        float w = g_pw[e];
        float4 v = act[((size_t)sn << sh) + c];
        acc.x += v.x * w; acc.y += v.y * w; acc.z += v.z * w; acc.w += v.w * w;
    }
    out[i] = acc;
}

// ---------------------------------------------------------------------------
// SGEMM with fused bias+relu, packed-fp32 FFMA2 inner product:
//   g_bufA[N,C] = relu(g_bufB[N,K] @ W[K,C] + bias)
// BM=BN=128, BK=8, 256 threads, 8x8 microtile. acc = 8 rows x 4 col-pairs
// of f32x2. B pairs come pre-packed from smem (ulonglong2 loads); A is
// broadcast-duplicated with one mov.b64 per row per k.
// ---------------------------------------------------------------------------
__global__ __launch_bounds__(256) void k_gemm_relu(const float* __restrict__ W,
                                                   const float* __restrict__ bias,
                                                   int Nrows, int K, int C) {
    __shared__ __align__(16) float As[8][132];
    __shared__ __align__(16) float Bs[8][132];

    const float* A = g_bufB;
    float* const out = g_bufA;

    int tid = threadIdx.x;
    int tx = tid & 15;          // 0..15 -> cols tx*4 and 64+tx*4
    int ty = tid >> 4;          // 0..15 -> rows ty*4 and 64+ty*4
    int row0 = blockIdx.y * 128;
    int col0 = blockIdx.x * 128;

    unsigned long long acc[8][4];
#pragma unroll
    for (int i = 0; i < 8; i++)
#pragma unroll
        for (int j = 0; j < 4; j++) acc[i][j] = 0ull;

    int ar = tid >> 1;               // A tile row 0..127
    int ak = (tid & 1) * 4;          // 0 or 4
    int bk = tid >> 5;               // 0..7
    int bc = (tid & 31) * 4;         // B tile col

    for (int kt = 0; kt < K; kt += 8) {
        int grow = row0 + ar;
        float4 av = make_float4(0.f, 0.f, 0.f, 0.f);
        if (grow < Nrows) av = *(const float4*)&A[(size_t)grow * K + kt + ak];
        As[ak + 0][ar] = av.x;
        As[ak + 1][ar] = av.y;
        As[ak + 2][ar] = av.z;
        As[ak + 3][ar] = av.w;

        *(float4*)&Bs[bk][bc] = *(const float4*)&W[(size_t)(kt + bk) * C + col0 + bc];
        __syncthreads();

#pragma unroll
        for (int k = 0; k < 8; k++) {
            float4 a0 = *(const float4*)&As[k][ty * 4];
            float4 a1 = *(const float4*)&As[k][64 + ty * 4];
            ulonglong2 bq0 = *(const ulonglong2*)&Bs[k][tx * 4];
            ulonglong2 bq1 = *(const ulonglong2*)&Bs[k][64 + tx * 4];
            unsigned long long bp[4] = {bq0.x, bq0.y, bq1.x, bq1.y};
            float aa[8] = {a0.x, a0.y, a0.z, a0.w, a1.x, a1.y, a1.z, a1.w};
#pragma unroll
            for (int i = 0; i < 8; i++) {
                unsigned long long ad;
                asm("mov.b64 %0, {%1, %1};" : "=l"(ad) : "f"(aa[i]));
#pragma unroll
                for (int j = 0; j < 4; j++)
                    asm("fma.rn.f32x2 %0, %1, %2, %0;"
                        : "+l"(acc[i][j]) : "l"(ad), "l"(bp[j]));
            }
        }
        __syncthreads();
    }

    float4 bv0 = *(const float4*)&bias[col0 + tx * 4];
    float4 bv1 = *(const float4*)&bias[col0 + 64 + tx * 4];

#pragma unroll
    for (int i = 0; i < 8; i++) {
        int grow = row0 + ((i < 4) ? (ty * 4 + i) : (64 + ty * 4 + i - 4));
        if (grow >= Nrows) continue;
        float2 u0, u1, u2, u3;
        asm("mov.b64 {%0, %1}, %2;" : "=f"(u0.x), "=f"(u0.y) : "l"(acc[i][0]));
        asm("mov.b64 {%0, %1}, %2;" : "=f"(u1.x), "=f"(u1.y) : "l"(acc[i][1]));
        asm("mov.b64 {%0, %1}, %2;" : "=f"(u2.x), "=f"(u2.y) : "l"(acc[i][2]));
        asm("mov.b64 {%0, %1}, %2;" : "=f"(u3.x), "=f"(u3.y) : "l"(acc[i][3]));
        float4 o0 = make_float4(fmaxf(u0.x + bv0.x, 0.f), fmaxf(u0.y + bv0.y, 0.f),
                                fmaxf(u1.x + bv0.z, 0.f), fmaxf(u1.y + bv0.w, 0.f));
        float4 o1 = make_float4(fmaxf(u2.x + bv1.x, 0.f), fmaxf(u2.y + bv1.y, 0.f),
                                fmaxf(u3.x + bv1.z, 0.f), fmaxf(u3.y + bv1.w, 0.f));
        *(float4*)&out[(size_t)grow * C + col0 + tx * 4] = o0;
        *(float4*)&out[(size_t)grow * C + col0 + 64 + tx * 4] = o1;
    }
}

// ---------------------------------------------------------------------------
// mean pool over g_bufA (final activations, 512 ch). No atomics.
// ---------------------------------------------------------------------------
__global__ __launch_bounds__(128) void k_pool() {
    int g = blockIdx.x;
    int c = blockIdx.y * 128 + threadIdx.x;
    int n0 = g_bnd[g];
    int n1 = g_bnd[g + 1];
    float acc = 0.f;
    for (int n = n0; n < n1; n++) acc += g_bufA[(size_t)n * 512 + c];
    float cntf = (float)(n1 - n0);
    g_pooled[g * 512 + c] = acc / fmaxf(cntf, 1.f);
}

// ---------------------------------------------------------------------------
__global__ __launch_bounds__(256) void k_dense(int in_sel,
                                               const float* __restrict__ W,
                                               const float* __restrict__ ba,
                                               const float* __restrict__ bb,
                                               float* out_ext, int In, int Out) {
    __shared__ __align__(16) float sin[512];
    const float* in = in_sel ? g_hl : g_pooled;
    float* out = out_ext ? out_ext : g_gates;
    int g = blockIdx.y;
    for (int k = threadIdx.x; k < In; k += blockDim.x) sin[k] = in[(size_t)g * In + k];
    __syncthreads();
    int j = blockIdx.x * blockDim.x + threadIdx.x;
    if (j >= Out) return;
    float acc = ba[j] + (bb ? bb[j] : 0.f);
    const float4* Wr = (const float4*)(W + (size_t)j * In);
    const float4* xs = (const float4*)sin;
    int k4 = In >> 2;
    for (int k = 0; k < k4; k++) {
        float4 w = Wr[k];
        float4 x = xs[k];
        acc += w.x * x.x + w.y * x.y + w.z * x.z + w.w * x.w;
    }
    out[(size_t)g * Out + j] = acc;
}

// h0=c0=0:  h = sigmoid(o) * tanh( sigmoid(i) * tanh(g) )
__global__ void k_lstm(int total, int H) {
    int i = blockIdx.x * blockDim.x + threadIdx.x;
    if (i >= total) return;
    int g = i / H;
    int j = i - g * H;
    const float* gr = g_gates + (size_t)g * 4 * H;
    float ii = gr[j];
    float gg = gr[2 * H + j];
    float oo = gr[3 * H + j];
    float si = 1.f / (1.f + expf(-ii));
    float so = 1.f / (1.f + expf(-oo));
    float c = si * tanhf(gg);
    g_hl[i] = so * tanhf(c);
}

// ---------------------------------------------------------------------------
extern "C" void kernel_launch(void* const* d_in, const int* in_sizes, int n_in,
                              void* d_out, int out_size) {
    const float* x     = (const float*)d_in[0];
    const void*  ei    = d_in[1];
    const void*  batch = d_in[2];
    const float *W1 = (const float*)d_in[3],  *b1 = (const float*)d_in[4];
    const float *W2 = (const float*)d_in[5],  *b2 = (const float*)d_in[6];
    const float *W3 = (const float*)d_in[7],  *b3 = (const float*)d_in[8];
    const float *Wih0 = (const float*)d_in[9];
    const float *bih0 = (const float*)d_in[11], *bhh0 = (const float*)d_in[12];
    const float *Wih1 = (const float*)d_in[13];
    const float *bih1 = (const float*)d_in[15], *bhh1 = (const float*)d_in[16];
    const float *Wp = (const float*)d_in[17],  *bp = (const float*)d_in[18];
    // Whh0 (d_in[10]) / Whh1 (d_in[14]) are dead: h0 = 0.

    int N = in_sizes[0] / 32;
    int E = in_sizes[1] / 2;
    int G = out_size / 512;

    const int T = 256;

    // ---- setup: dtype sniff + CSR build + norms + graph bounds (4 kernels) ----
    k_detect_zero<<<cdiv(N, T), T>>>((const int*)ei, in_sizes[1],
                                     (const int*)batch, in_sizes[2], N);
    k_count<<<cdiv(E, T), T>>>(ei, E, N);
    k_prep<<<1, 1024>>>(batch, N, G);
    k_place<<<cdiv(E, T), T>>>(ei, E, N);

    // ---- GCN layer 1: agg(x)[N,32] -> relu(@W1+b1)[N,128] ----
    k_agg<<<cdiv(N * 8, T), T>>>(0, x, N * 8, 3);
    k_gemm_relu<<<dim3(1, cdiv(N, 128)), 256>>>(W1, b1, N, 32, 128);

    // ---- GCN layer 2: agg[N,128] -> relu(@W2+b2)[N,256] ----
    k_agg<<<cdiv(N * 32, T), T>>>(1, nullptr, N * 32, 5);
    k_gemm_relu<<<dim3(2, cdiv(N, 128)), 256>>>(W2, b2, N, 128, 256);

    // ---- GCN layer 3: agg[N,256] -> relu(@W3+b3)[N,512] ----
    k_agg<<<cdiv(N * 64, T), T>>>(1, nullptr, N * 64, 6);
    k_gemm_relu<<<dim3(4, cdiv(N, 128)), 256>>>(W3, b3, N, 256, 512);

    // ---- mean pool per graph ----
    k_pool<<<dim3(G, 4), 128>>>();

    // ---- LSTM (degenerate) + projection ----
    k_dense<<<dim3(4, G), 256>>>(0, Wih0, bih0, bhh0, nullptr, 512, 1024);
    k_lstm<<<cdiv(G * 256, T), T>>>(G * 256, 256);
    k_dense<<<dim3(4, G), 256>>>(1, Wih1, bih1, bhh1, nullptr, 256, 1024);
    k_lstm<<<cdiv(G * 256, T), T>>>(G * 256, 256);
    k_dense<<<dim3(2, G), 256>>>(1, Wp, bp, nullptr, (float*)d_out, 256, 512);
}

// round 16
// speedup vs baseline: 1.3389x; 1.2086x over previous
#include <cuda_runtime.h>
#include <cuda_bf16.h>

// ---------------------------------------------------------------------------
// NodeLevelEncoder: 3x GCN + mean pool + 2x degenerate LSTM + projection.
// R15: GEMM on tensor cores via bf16 mma.sync.m16n8k16 with hi/lo split
// (3 MMAs: hh + hl + lh => ~2^-18 input precision). Conversions hoisted out
// of the mainloop: k_agg writes packed bf16 hi/lo planes; W pre-split once
// per layer. Agg-before-transform retained.
// ---------------------------------------------------------------------------

#define MAXN 100000
#define MAXE 800000
#define MAXG 64

__device__ __align__(16) float g_bufA[(size_t)MAXN * 512];          // activations (GEMM out, fp32)
__device__ __align__(16) unsigned short g_bufH[(size_t)MAXN * 256]; // agg hi plane (bf16)
__device__ __align__(16) unsigned short g_bufL[(size_t)MAXN * 256]; // agg lo plane (bf16)
__device__ __align__(16) unsigned g_wh[128 * 512];                  // W hi, k-pair packed
__device__ __align__(16) unsigned g_wl[128 * 512];                  // W lo, k-pair packed
__device__ float g_dinv[MAXN];
__device__ int   g_icnt[MAXN];
__device__ int   g_off[MAXN];
__device__ int   g_cur[MAXN];
__device__ int   g_psrc[MAXE];
__device__ float g_pw[MAXE];
__device__ int   g_bnd[MAXG + 1];
__device__ __align__(16) float g_pooled[MAXG * 512];
__device__ __align__(16) float g_gates[MAXG * 1024];
__device__ __align__(16) float g_hl[MAXG * 256];
__device__ int   g_w64;
__device__ int   g_b64;

static inline int cdiv(int a, int b) { return (a + b - 1) / b; }

// ---------------------------------------------------------------------------
// setup: zero counters + dtype sniff (int64 LE => odd int32 slots are 0)
__global__ void k_detect_zero(const int* ei32, int eslots, const int* b32,
                              int bslots, int N) {
    int i = blockIdx.x * blockDim.x + threadIdx.x;
    if (i < N) { g_icnt[i] = 0; g_cur[i] = 0; }
    if (blockIdx.x == 0 && threadIdx.x == 0) {
        int w64 = 1;
        for (int k = 0; k < 64; k++) {
            long long j = ((long long)(2 * k + 1) * eslots) / 128;
            int idx = (int)(j | 1);
            if (idx < eslots && ei32[idx] != 0) { w64 = 0; break; }
        }
        g_w64 = w64;
        int b64 = 1;
        for (int k = 0; k < 64; k++) {
            long long j = ((long long)(2 * k + 1) * bslots) / 128;
            int idx = (int)(j | 1);
            if (idx < bslots && b32[idx] != 0) { b64 = 0; break; }
        }
        g_b64 = b64;
    }
}

__device__ __forceinline__ int load_idx(const void* p, long long i, int is64) {
    return is64 ? (int)((const long long*)p)[i] : ((const int*)p)[i];
}

__global__ void k_count(const void* __restrict__ ei, int E, int N) {
    int e = blockIdx.x * blockDim.x + threadIdx.x;
    if (e >= E) return;
    int d = load_idx(ei, (long long)E + e, g_w64);
    if ((unsigned)d < (unsigned)N) atomicAdd(&g_icnt[d], 1);
}

// dinv + exclusive scan + per-graph bounds, one block
__global__ __launch_bounds__(1024) void k_prep(const void* __restrict__ batch,
                                               int N, int G) {
    __shared__ int ssum[1024];
    int tid = threadIdx.x;
    int chunk = (N + 1023) >> 10;
    int a0 = tid * chunk;
    int a1 = min(a0 + chunk, N);
    int s = 0;
    for (int i = a0; i < a1; i++) {
        int c = g_icnt[i];
        g_dinv[i] = rsqrtf((float)c + 1.0f);
        s += c;
    }
    ssum[tid] = s;
    __syncthreads();
    for (int d = 1; d < 1024; d <<= 1) {
        int v = (tid >= d) ? ssum[tid - d] : 0;
        __syncthreads();
        ssum[tid] += v;
        __syncthreads();
    }
    int run = (tid == 0) ? 0 : ssum[tid - 1];
    for (int i = a0; i < a1; i++) { g_off[i] = run; run += g_icnt[i]; }

    if (tid <= G) {
        if (tid == G) g_bnd[G] = N;
        else {
            int b64 = g_b64;
            int lo = 0, hi = N;
            while (lo < hi) {
                int mid = (lo + hi) >> 1;
                if (load_idx(batch, mid, b64) < tid) lo = mid + 1; else hi = mid;
            }
            g_bnd[tid] = lo;
        }
    }
}

__global__ void k_place(const void* __restrict__ ei, int E, int N) {
    int e = blockIdx.x * blockDim.x + threadIdx.x;
    if (e >= E) return;
    int w64 = g_w64;
    int s = load_idx(ei, e, w64);
    int d = load_idx(ei, (long long)E + e, w64);
    if ((unsigned)s >= (unsigned)N || (unsigned)d >= (unsigned)N) return;
    int p = atomicAdd(&g_cur[d], 1);
    int o = g_off[d] + p;
    g_psrc[o] = s;
    g_pw[o] = g_dinv[s] * g_dinv[d];
}

// ---------------------------------------------------------------------------
// helpers: bf16 hi/lo split + pack
__device__ __forceinline__ unsigned pack_bf16(float a, float b) {
    unsigned short ua = __bfloat16_as_ushort(__float2bfloat16(a));
    unsigned short ub = __bfloat16_as_ushort(__float2bfloat16(b));
    return ((unsigned)ub << 16) | ua;
}

// ---------------------------------------------------------------------------
// W pre-split: Wp[k2*C + n] packs (W[2k2][n], W[2k2+1][n]) as bf16 hi/lo.
__global__ void k_wsplit(const float* __restrict__ W, int K, int C) {
    int i = blockIdx.x * blockDim.x + threadIdx.x;
    if (i >= (K / 2) * C) return;
    int k2 = i / C, n = i - k2 * C;
    float w0 = W[(size_t)(2 * k2) * C + n];
    float w1 = W[(size_t)(2 * k2 + 1) * C + n];
    float h0 = __bfloat162float(__float2bfloat16(w0));
    float h1 = __bfloat162float(__float2bfloat16(w1));
    g_wh[i] = pack_bf16(h0, h1);
    g_wl[i] = pack_bf16(w0 - h0, w1 - h1);
}

// ---------------------------------------------------------------------------
// GCN aggregation in INPUT dim; writes packed bf16 hi/lo planes.
// One thread per (node, float4 group). sh = log2(K/4).
// ---------------------------------------------------------------------------
__global__ void k_agg(int a_sel, const float* __restrict__ ext, int total, int sh) {
    int i = blockIdx.x * blockDim.x + threadIdx.x;
    if (i >= total) return;
    int n = i >> sh;
    int c = i & ((1 << sh) - 1);

    const float4* act = a_sel ? (const float4*)g_bufA : (const float4*)ext;

    float s = g_dinv[n];
    s *= s;
    float4 t = act[i];
    float4 acc = make_float4(t.x * s, t.y * s, t.z * s, t.w * s);

    int e0 = g_off[n];
    int e1 = e0 + g_icnt[n];
    for (int e = e0; e < e1; e++) {
        int sn = g_psrc[e];
        float w = g_pw[e];
        float4 v = act[((size_t)sn << sh) + c];
        acc.x += v.x * w; acc.y += v.y * w; acc.z += v.z * w; acc.w += v.w * w;
    }

    float hx = __bfloat162float(__float2bfloat16(acc.x));
    float hy = __bfloat162float(__float2bfloat16(acc.y));
    float hz = __bfloat162float(__float2bfloat16(acc.z));
    float hw = __bfloat162float(__float2bfloat16(acc.w));
    uint2 uh = make_uint2(pack_bf16(hx, hy), pack_bf16(hz, hw));
    uint2 ul = make_uint2(pack_bf16(acc.x - hx, acc.y - hy),
                          pack_bf16(acc.z - hz, acc.w - hw));
    ((uint2*)g_bufH)[i] = uh;
    ((uint2*)g_bufL)[i] = ul;
}

// ---------------------------------------------------------------------------
// bf16 tensor-core GEMM, 3-MMA hi/lo compensation, fused bias+relu:
//   g_bufA[N,C] = relu(A[N,K] @ W[K,C] + bias),  A = (g_bufH,g_bufL) planes
// BM=BN=128, BK=32. 256 thr = 8 warps (2m x 4n), warp tile 64x32 =
// 4x4 tiles of m16n8k16 x 2 k-steps. K in {32,128,256}, C in {128,256,512}.
// ---------------------------------------------------------------------------
__device__ __forceinline__ void mma_bf16(float c[4], unsigned a0, unsigned a1,
                                         unsigned a2, unsigned a3,
                                         unsigned b0, unsigned b1) {
    asm("mma.sync.aligned.m16n8k16.row.col.f32.bf16.bf16.f32 "
        "{%0,%1,%2,%3},{%4,%5,%6,%7},{%8,%9},{%0,%1,%2,%3};"
        : "+f"(c[0]), "+f"(c[1]), "+f"(c[2]), "+f"(c[3])
        : "r"(a0), "r"(a1), "r"(a2), "r"(a3), "r"(b0), "r"(b1));
}

__global__ __launch_bounds__(256) void k_gemm_bf16(const float* __restrict__ bias,
                                                   int Nrows, int K, int C) {
    // A planes: [128 rows][20 uints] (16 data + 4 pad) — frag loads conflict-free
    // B planes: [16 k2-rows][136 uints] (128 data + 8 pad) — tig*8+gid distinct
    __shared__ __align__(16) unsigned AsH[128][20], AsL[128][20];
    __shared__ __align__(16) unsigned BsH[16][136], BsL[16][136];

    const unsigned* AH = (const unsigned*)g_bufH;
    const unsigned* AL = (const unsigned*)g_bufL;
    float* const out = g_bufA;

    int tid = threadIdx.x;
    int wid = tid >> 5, lane = tid & 31;
    int gid = lane >> 2, tig = lane & 3;
    int wm = wid & 1, wn = wid >> 1;
    int row0 = blockIdx.y * 128, col0 = blockIdx.x * 128;
    int mbase = wm * 64, nbase = wn * 32;
    int Ku = K >> 1;                       // uints per A row

    float acc[4][4][4];
#pragma unroll
    for (int mt = 0; mt < 4; mt++)
#pragma unroll
        for (int nt = 0; nt < 4; nt++)
#pragma unroll
            for (int r = 0; r < 4; r++) acc[mt][nt][r] = 0.f;

    int ar = tid >> 1;                 // A stage row 0..127
    int au = (tid & 1) * 8;            // uint col 0 or 8
    int bk = tid >> 4;                 // B stage k2-row 0..15
    int bn = (tid & 15) * 8;           // B stage col

    for (int kt = 0; kt < K; kt += 32) {
        int ktu = kt >> 1;
        int grow = row0 + ar;
        uint4 h = make_uint4(0, 0, 0, 0), h2 = h, l = h, l2 = h;
        if (grow < Nrows) {
            const unsigned* ph = &AH[(size_t)grow * Ku + ktu + au];
            const unsigned* pl = &AL[(size_t)grow * Ku + ktu + au];
            h = *(const uint4*)ph; h2 = *(const uint4*)(ph + 4);
            l = *(const uint4*)pl; l2 = *(const uint4*)(pl + 4);
        }
        *(uint4*)&AsH[ar][au] = h;  *(uint4*)&AsH[ar][au + 4] = h2;
        *(uint4*)&AsL[ar][au] = l;  *(uint4*)&AsL[ar][au + 4] = l2;

        {
            const unsigned* ph = &g_wh[(size_t)(ktu + bk) * C + col0 + bn];
            const unsigned* pl = &g_wl[(size_t)(ktu + bk) * C + col0 + bn];
            *(uint4*)&BsH[bk][bn] = *(const uint4*)ph;
            *(uint4*)&BsH[bk][bn + 4] = *(const uint4*)(ph + 4);
            *(uint4*)&BsL[bk][bn] = *(const uint4*)pl;
            *(uint4*)&BsL[bk][bn + 4] = *(const uint4*)(pl + 4);
        }
        __syncthreads();

#pragma unroll
        for (int ks = 0; ks < 2; ks++) {
            int u0 = ks * 8 + tig;
            unsigned ah[4][4], al[4][4];
#pragma unroll
            for (int mt = 0; mt < 4; mt++) {
                int m = mbase + mt * 16 + gid;
                ah[mt][0] = AsH[m][u0];     ah[mt][1] = AsH[m + 8][u0];
                ah[mt][2] = AsH[m][u0 + 4]; ah[mt][3] = AsH[m + 8][u0 + 4];
                al[mt][0] = AsL[m][u0];     al[mt][1] = AsL[m + 8][u0];
                al[mt][2] = AsL[m][u0 + 4]; al[mt][3] = AsL[m + 8][u0 + 4];
            }
            unsigned bh[4][2], bl[4][2];
#pragma unroll
            for (int nt = 0; nt < 4; nt++) {
                int n = nbase + nt * 8 + gid;
                bh[nt][0] = BsH[ks * 8 + tig][n];
                bh[nt][1] = BsH[ks * 8 + tig + 4][n];
                bl[nt][0] = BsL[ks * 8 + tig][n];
                bl[nt][1] = BsL[ks * 8 + tig + 4][n];
            }
#pragma unroll
            for (int mt = 0; mt < 4; mt++)
#pragma unroll
                for (int nt = 0; nt < 4; nt++) {
                    mma_bf16(acc[mt][nt], ah[mt][0], ah[mt][1], ah[mt][2], ah[mt][3],
                             bh[nt][0], bh[nt][1]);
                    mma_bf16(acc[mt][nt], ah[mt][0], ah[mt][1], ah[mt][2], ah[mt][3],
                             bl[nt][0], bl[nt][1]);
                    mma_bf16(acc[mt][nt], al[mt][0], al[mt][1], al[mt][2], al[mt][3],
                             bh[nt][0], bh[nt][1]);
                }
        }
        __syncthreads();
    }

    // epilogue: bias + relu -> fp32 activations
#pragma unroll
    for (int mt = 0; mt < 4; mt++) {
#pragma unroll
        for (int nt = 0; nt < 4; nt++) {
            int col = col0 + nbase + nt * 8 + tig * 2;
            float bx = bias[col], by = bias[col + 1];
            int r0 = row0 + mbase + mt * 16 + gid;
            if (r0 < Nrows) {
                float2 o;
                o.x = fmaxf(acc[mt][nt][0] + bx, 0.f);
                o.y = fmaxf(acc[mt][nt][1] + by, 0.f);
                *(float2*)&out[(size_t)r0 * C + col] = o;
            }
            int r1 = r0 + 8;
            if (r1 < Nrows) {
                float2 o;
                o.x = fmaxf(acc[mt][nt][2] + bx, 0.f);
                o.y = fmaxf(acc[mt][nt][3] + by, 0.f);
                *(float2*)&out[(size_t)r1 * C + col] = o;
            }
        }
    }
}

// ---------------------------------------------------------------------------
// mean pool over g_bufA (final activations, 512 ch). No atomics.
// ---------------------------------------------------------------------------
__global__ __launch_bounds__(128) void k_pool() {
    int g = blockIdx.x;
    int c = blockIdx.y * 128 + threadIdx.x;
    int n0 = g_bnd[g];
    int n1 = g_bnd[g + 1];
    float acc = 0.f;
    for (int n = n0; n < n1; n++) acc += g_bufA[(size_t)n * 512 + c];
    float cntf = (float)(n1 - n0);
    g_pooled[g * 512 + c] = acc / fmaxf(cntf, 1.f);
}

// ---------------------------------------------------------------------------
__global__ __launch_bounds__(256) void k_dense(int in_sel,
                                               const float* __restrict__ W,
                                               const float* __restrict__ ba,
                                               const float* __restrict__ bb,
                                               float* out_ext, int In, int Out) {
    __shared__ __align__(16) float sin[512];
    const float* in = in_sel ? g_hl : g_pooled;
    float* out = out_ext ? out_ext : g_gates;
    int g = blockIdx.y;
    for (int k = threadIdx.x; k < In; k += blockDim.x) sin[k] = in[(size_t)g * In + k];
    __syncthreads();
    int j = blockIdx.x * blockDim.x + threadIdx.x;
    if (j >= Out) return;
    float acc = ba[j] + (bb ? bb[j] : 0.f);
    const float4* Wr = (const float4*)(W + (size_t)j * In);
    const float4* xs = (const float4*)sin;
    int k4 = In >> 2;
    for (int k = 0; k < k4; k++) {
        float4 w = Wr[k];
        float4 x = xs[k];
        acc += w.x * x.x + w.y * x.y + w.z * x.z + w.w * x.w;
    }
    out[(size_t)g * Out + j] = acc;
}

// h0=c0=0:  h = sigmoid(o) * tanh( sigmoid(i) * tanh(g) )
__global__ void k_lstm(int total, int H) {
    int i = blockIdx.x * blockDim.x + threadIdx.x;
    if (i >= total) return;
    int g = i / H;
    int j = i - g * H;
    const float* gr = g_gates + (size_t)g * 4 * H;
    float ii = gr[j];
    float gg = gr[2 * H + j];
    float oo = gr[3 * H + j];
    float si = 1.f / (1.f + expf(-ii));
    float so = 1.f / (1.f + expf(-oo));
    float c = si * tanhf(gg);
    g_hl[i] = so * tanhf(c);
}

// ---------------------------------------------------------------------------
extern "C" void kernel_launch(void* const* d_in, const int* in_sizes, int n_in,
                              void* d_out, int out_size) {
    const float* x     = (const float*)d_in[0];
    const void*  ei    = d_in[1];
    const void*  batch = d_in[2];
    const float *W1 = (const float*)d_in[3],  *b1 = (const float*)d_in[4];
    const float *W2 = (const float*)d_in[5],  *b2 = (const float*)d_in[6];
    const float *W3 = (const float*)d_in[7],  *b3 = (const float*)d_in[8];
    const float *Wih0 = (const float*)d_in[9];
    const float *bih0 = (const float*)d_in[11], *bhh0 = (const float*)d_in[12];
    const float *Wih1 = (const float*)d_in[13];
    const float *bih1 = (const float*)d_in[15], *bhh1 = (const float*)d_in[16];
    const float *Wp = (const float*)d_in[17],  *bp = (const float*)d_in[18];
    // Whh0 (d_in[10]) / Whh1 (d_in[14]) are dead: h0 = 0.

    int N = in_sizes[0] / 32;
    int E = in_sizes[1] / 2;
    int G = out_size / 512;

    const int T = 256;

    // ---- setup: dtype sniff + CSR build + norms + graph bounds ----
    k_detect_zero<<<cdiv(N, T), T>>>((const int*)ei, in_sizes[1],
                                     (const int*)batch, in_sizes[2], N);
    k_count<<<cdiv(E, T), T>>>(ei, E, N);
    k_prep<<<1, 1024>>>(batch, N, G);
    k_place<<<cdiv(E, T), T>>>(ei, E, N);

    // ---- GCN layer 1: agg(x)[N,32] -> relu(@W1+b1)[N,128] ----
    k_wsplit<<<cdiv(16 * 128, T), T>>>(W1, 32, 128);
    k_agg<<<cdiv(N * 8, T), T>>>(0, x, N * 8, 3);
    k_gemm_bf16<<<dim3(1, cdiv(N, 128)), 256>>>(b1, N, 32, 128);

    // ---- GCN layer 2: agg[N,128] -> relu(@W2+b2)[N,256] ----
    k_wsplit<<<cdiv(64 * 256, T), T>>>(W2, 128, 256);
    k_agg<<<cdiv(N * 32, T), T>>>(1, nullptr, N * 32, 5);
    k_gemm_bf16<<<dim3(2, cdiv(N, 128)), 256>>>(b2, N, 128, 256);

    // ---- GCN layer 3: agg[N,256] -> relu(@W3+b3)[N,512] ----
    k_wsplit<<<cdiv(128 * 512, T), T>>>(W3, 256, 512);
    k_agg<<<cdiv(N * 64, T), T>>>(1, nullptr, N * 64, 6);
    k_gemm_bf16<<<dim3(4, cdiv(N, 128)), 256>>>(b3, N, 256, 512);

    // ---- mean pool per graph ----
    k_pool<<<dim3(G, 4), 128>>>();

    // ---- LSTM (degenerate) + projection ----
    k_dense<<<dim3(4, G), 256>>>(0, Wih0, bih0, bhh0, nullptr, 512, 1024);
    k_lstm<<<cdiv(G * 256, T), T>>>(G * 256, 256);
    k_dense<<<dim3(4, G), 256>>>(1, Wih1, bih1, bhh1, nullptr, 256, 1024);
    k_lstm<<<cdiv(G * 256, T), T>>>(G * 256, 256);
    k_dense<<<dim3(2, G), 256>>>(1, Wp, bp, nullptr, (float*)d_out, 256, 512);
}

// round 17
// speedup vs baseline: 1.4651x; 1.0943x over previous
#include <cuda_runtime.h>
#include <cuda_bf16.h>

// ---------------------------------------------------------------------------
// NodeLevelEncoder: 3x GCN + mean pool + 2x degenerate LSTM + projection.
// R17: bf16 hi/lo tensor-core GEMM (3-MMA compensation) with ALL fragment
// loads via ldmatrix (LDSM) instead of scalar LDS; W pre-split is stored
// transposed [n][k2] so B fragments are ldmatrix-compatible.
// ---------------------------------------------------------------------------

#define MAXN 100000
#define MAXE 800000
#define MAXG 64

__device__ __align__(16) float g_bufA[(size_t)MAXN * 512];          // activations (fp32)
__device__ __align__(16) unsigned short g_bufH[(size_t)MAXN * 256]; // agg hi plane (bf16)
__device__ __align__(16) unsigned short g_bufL[(size_t)MAXN * 256]; // agg lo plane (bf16)
__device__ __align__(16) unsigned g_wh[512 * 128];                  // W^T hi, [n][k2]
__device__ __align__(16) unsigned g_wl[512 * 128];                  // W^T lo, [n][k2]
__device__ float g_dinv[MAXN];
__device__ int   g_icnt[MAXN];
__device__ int   g_off[MAXN];
__device__ int   g_cur[MAXN];
__device__ int   g_psrc[MAXE];
__device__ float g_pw[MAXE];
__device__ int   g_bnd[MAXG + 1];
__device__ __align__(16) float g_pooled[MAXG * 512];
__device__ __align__(16) float g_gates[MAXG * 1024];
__device__ __align__(16) float g_hl[MAXG * 256];
__device__ int   g_w64;
__device__ int   g_b64;

static inline int cdiv(int a, int b) { return (a + b - 1) / b; }

// ---------------------------------------------------------------------------
__global__ void k_detect_zero(const int* ei32, int eslots, const int* b32,
                              int bslots, int N) {
    int i = blockIdx.x * blockDim.x + threadIdx.x;
    if (i < N) { g_icnt[i] = 0; g_cur[i] = 0; }
    if (blockIdx.x == 0 && threadIdx.x == 0) {
        int w64 = 1;
        for (int k = 0; k < 64; k++) {
            long long j = ((long long)(2 * k + 1) * eslots) / 128;
            int idx = (int)(j | 1);
            if (idx < eslots && ei32[idx] != 0) { w64 = 0; break; }
        }
        g_w64 = w64;
        int b64 = 1;
        for (int k = 0; k < 64; k++) {
            long long j = ((long long)(2 * k + 1) * bslots) / 128;
            int idx = (int)(j | 1);
            if (idx < bslots && b32[idx] != 0) { b64 = 0; break; }
        }
        g_b64 = b64;
    }
}

__device__ __forceinline__ int load_idx(const void* p, long long i, int is64) {
    return is64 ? (int)((const long long*)p)[i] : ((const int*)p)[i];
}

__global__ void k_count(const void* __restrict__ ei, int E, int N) {
    int e = blockIdx.x * blockDim.x + threadIdx.x;
    if (e >= E) return;
    int d = load_idx(ei, (long long)E + e, g_w64);
    if ((unsigned)d < (unsigned)N) atomicAdd(&g_icnt[d], 1);
}

__global__ __launch_bounds__(1024) void k_prep(const void* __restrict__ batch,
                                               int N, int G) {
    __shared__ int ssum[1024];
    int tid = threadIdx.x;
    int chunk = (N + 1023) >> 10;
    int a0 = tid * chunk;
    int a1 = min(a0 + chunk, N);
    int s = 0;
    for (int i = a0; i < a1; i++) {
        int c = g_icnt[i];
        g_dinv[i] = rsqrtf((float)c + 1.0f);
        s += c;
    }
    ssum[tid] = s;
    __syncthreads();
    for (int d = 1; d < 1024; d <<= 1) {
        int v = (tid >= d) ? ssum[tid - d] : 0;
        __syncthreads();
        ssum[tid] += v;
        __syncthreads();
    }
    int run = (tid == 0) ? 0 : ssum[tid - 1];
    for (int i = a0; i < a1; i++) { g_off[i] = run; run += g_icnt[i]; }

    if (tid <= G) {
        if (tid == G) g_bnd[G] = N;
        else {
            int b64 = g_b64;
            int lo = 0, hi = N;
            while (lo < hi) {
                int mid = (lo + hi) >> 1;
                if (load_idx(batch, mid, b64) < tid) lo = mid + 1; else hi = mid;
            }
            g_bnd[tid] = lo;
        }
    }
}

__global__ void k_place(const void* __restrict__ ei, int E, int N) {
    int e = blockIdx.x * blockDim.x + threadIdx.x;
    if (e >= E) return;
    int w64 = g_w64;
    int s = load_idx(ei, e, w64);
    int d = load_idx(ei, (long long)E + e, w64);
    if ((unsigned)s >= (unsigned)N || (unsigned)d >= (unsigned)N) return;
    int p = atomicAdd(&g_cur[d], 1);
    int o = g_off[d] + p;
    g_psrc[o] = s;
    g_pw[o] = g_dinv[s] * g_dinv[d];
}

// ---------------------------------------------------------------------------
__device__ __forceinline__ unsigned pack_bf16(float a, float b) {
    unsigned short ua = __bfloat16_as_ushort(__float2bfloat16(a));
    unsigned short ub = __bfloat16_as_ushort(__float2bfloat16(b));
    return ((unsigned)ub << 16) | ua;
}

// W pre-split, TRANSPOSED: g_wh[n*Ku + k2] packs (W[2k2][n], W[2k2+1][n]).
__global__ void k_wsplit(const float* __restrict__ W, int K, int C) {
    int Ku = K >> 1;
    int i = blockIdx.x * blockDim.x + threadIdx.x;
    if (i >= Ku * C) return;
    int n = i / Ku, k2 = i - n * Ku;
    float w0 = W[(size_t)(2 * k2) * C + n];
    float w1 = W[(size_t)(2 * k2 + 1) * C + n];
    float h0 = __bfloat162float(__float2bfloat16(w0));
    float h1 = __bfloat162float(__float2bfloat16(w1));
    g_wh[i] = pack_bf16(h0, h1);
    g_wl[i] = pack_bf16(w0 - h0, w1 - h1);
}

// ---------------------------------------------------------------------------
// GCN aggregation in INPUT dim; writes packed bf16 hi/lo planes.
// ---------------------------------------------------------------------------
__global__ void k_agg(int a_sel, const float* __restrict__ ext, int total, int sh) {
    int i = blockIdx.x * blockDim.x + threadIdx.x;
    if (i >= total) return;
    int n = i >> sh;
    int c = i & ((1 << sh) - 1);

    const float4* act = a_sel ? (const float4*)g_bufA : (const float4*)ext;

    float s = g_dinv[n];
    s *= s;
    float4 t = act[i];
    float4 acc = make_float4(t.x * s, t.y * s, t.z * s, t.w * s);

    int e0 = g_off[n];
    int e1 = e0 + g_icnt[n];
    for (int e = e0; e < e1; e++) {
        int sn = g_psrc[e];
        float w = g_pw[e];
        float4 v = act[((size_t)sn << sh) + c];
        acc.x += v.x * w; acc.y += v.y * w; acc.z += v.z * w; acc.w += v.w * w;
    }

    float hx = __bfloat162float(__float2bfloat16(acc.x));
    float hy = __bfloat162float(__float2bfloat16(acc.y));
    float hz = __bfloat162float(__float2bfloat16(acc.z));
    float hw = __bfloat162float(__float2bfloat16(acc.w));
    uint2 uh = make_uint2(pack_bf16(hx, hy), pack_bf16(hz, hw));
    uint2 ul = make_uint2(pack_bf16(acc.x - hx, acc.y - hy),
                          pack_bf16(acc.z - hz, acc.w - hw));
    ((uint2*)g_bufH)[i] = uh;
    ((uint2*)g_bufL)[i] = ul;
}

// ---------------------------------------------------------------------------
// bf16 tensor-core GEMM, 3-MMA hi/lo, LDSM fragment loads, fused bias+relu.
// BM=BN=128, BK=32. 8 warps (2m x 4n), warp tile 64x32.
// ---------------------------------------------------------------------------
__device__ __forceinline__ void mma_bf16(float c[4], unsigned a0, unsigned a1,
                                         unsigned a2, unsigned a3,
                                         unsigned b0, unsigned b1) {
    asm("mma.sync.aligned.m16n8k16.row.col.f32.bf16.bf16.f32 "
        "{%0,%1,%2,%3},{%4,%5,%6,%7},{%8,%9},{%0,%1,%2,%3};"
        : "+f"(c[0]), "+f"(c[1]), "+f"(c[2]), "+f"(c[3])
        : "r"(a0), "r"(a1), "r"(a2), "r"(a3), "r"(b0), "r"(b1));
}

__device__ __forceinline__ void ldsm4(unsigned& r0, unsigned& r1, unsigned& r2,
                                      unsigned& r3, unsigned addr) {
    asm volatile("ldmatrix.sync.aligned.m8n8.x4.shared.b16 {%0,%1,%2,%3},[%4];"
                 : "=r"(r0), "=r"(r1), "=r"(r2), "=r"(r3) : "r"(addr));
}
__device__ __forceinline__ void ldsm2(unsigned& r0, unsigned& r1, unsigned addr) {
    asm volatile("ldmatrix.sync.aligned.m8n8.x2.shared.b16 {%0,%1},[%2];"
                 : "=r"(r0), "=r"(r1) : "r"(addr));
}

__global__ __launch_bounds__(256) void k_gemm_bf16(const float* __restrict__ bias,
                                                   int Nrows, int K, int C) {
    // A planes: [128 m][20 uints] (16 data + 4 pad); B planes: [128 n][20 uints]
    __shared__ __align__(16) unsigned AsH[128][20], AsL[128][20];
    __shared__ __align__(16) unsigned BsH[128][20], BsL[128][20];

    const unsigned* AH = (const unsigned*)g_bufH;
    const unsigned* AL = (const unsigned*)g_bufL;
    float* const out = g_bufA;

    int tid = threadIdx.x;
    int wid = tid >> 5, lane = tid & 31;
    int gid = lane >> 2, tig = lane & 3;
    int wm = wid & 1, wn = wid >> 1;
    int row0 = blockIdx.y * 128, col0 = blockIdx.x * 128;
    int mbase = wm * 64, nbase = wn * 32;
    int Ku = K >> 1;

    // LDSM lane->address offsets
    int a_row = (lane & 7) + ((lane & 8) ? 8 : 0);   // x4: m row within 16
    int a_col = (lane & 16) ? 4 : 0;                 // x4: k-pair quad
    int b_row = lane & 7;                            // x2: n row within 8
    int b_col = (lane & 8) ? 4 : 0;                  // x2: k-pair quad

    float acc[4][4][4];
#pragma unroll
    for (int mt = 0; mt < 4; mt++)
#pragma unroll
        for (int nt = 0; nt < 4; nt++)
#pragma unroll
            for (int r = 0; r < 4; r++) acc[mt][nt][r] = 0.f;

    int sr = tid >> 1;                 // stage row 0..127 (m for A, n for B)
    int su = (tid & 1) * 8;            // uint col 0 or 8

    for (int kt = 0; kt < K; kt += 32) {
        int ktu = kt >> 1;
        // stage A (hi/lo)
        int grow = row0 + sr;
        uint4 h = make_uint4(0, 0, 0, 0), h2 = h, l = h, l2 = h;
        if (grow < Nrows) {
            const unsigned* ph = &AH[(size_t)grow * Ku + ktu + su];
            const unsigned* pl = &AL[(size_t)grow * Ku + ktu + su];
            h = *(const uint4*)ph; h2 = *(const uint4*)(ph + 4);
            l = *(const uint4*)pl; l2 = *(const uint4*)(pl + 4);
        }
        *(uint4*)&AsH[sr][su] = h;  *(uint4*)&AsH[sr][su + 4] = h2;
        *(uint4*)&AsL[sr][su] = l;  *(uint4*)&AsL[sr][su + 4] = l2;
        // stage B (hi/lo) from transposed W planes [n][k2]
        {
            const unsigned* ph = &g_wh[(size_t)(col0 + sr) * Ku + ktu + su];
            const unsigned* pl = &g_wl[(size_t)(col0 + sr) * Ku + ktu + su];
            *(uint4*)&BsH[sr][su] = *(const uint4*)ph;
            *(uint4*)&BsH[sr][su + 4] = *(const uint4*)(ph + 4);
            *(uint4*)&BsL[sr][su] = *(const uint4*)pl;
            *(uint4*)&BsL[sr][su + 4] = *(const uint4*)(pl + 4);
        }
        __syncthreads();

#pragma unroll
        for (int ks = 0; ks < 2; ks++) {
            int kb = ks * 8;
            unsigned ah[4][4], al[4][4], bh[4][2], bl[4][2];
#pragma unroll
            for (int mt = 0; mt < 4; mt++) {
                int m = mbase + mt * 16 + a_row;
                unsigned adH = (unsigned)__cvta_generic_to_shared(&AsH[m][kb + a_col]);
                unsigned adL = (unsigned)__cvta_generic_to_shared(&AsL[m][kb + a_col]);
                ldsm4(ah[mt][0], ah[mt][1], ah[mt][2], ah[mt][3], adH);
                ldsm4(al[mt][0], al[mt][1], al[mt][2], al[mt][3], adL);
            }
#pragma unroll
            for (int nt = 0; nt < 4; nt++) {
                int n = nbase + nt * 8 + b_row;
                unsigned bdH = (unsigned)__cvta_generic_to_shared(&BsH[n][kb + b_col]);
                unsigned bdL = (unsigned)__cvta_generic_to_shared(&BsL[n][kb + b_col]);
                ldsm2(bh[nt][0], bh[nt][1], bdH);
                ldsm2(bl[nt][0], bl[nt][1], bdL);
            }
#pragma unroll
            for (int mt = 0; mt < 4; mt++)
#pragma unroll
                for (int nt = 0; nt < 4; nt++) {
                    mma_bf16(acc[mt][nt], ah[mt][0], ah[mt][1], ah[mt][2], ah[mt][3],
                             bh[nt][0], bh[nt][1]);
                    mma_bf16(acc[mt][nt], ah[mt][0], ah[mt][1], ah[mt][2], ah[mt][3],
                             bl[nt][0], bl[nt][1]);
                    mma_bf16(acc[mt][nt], al[mt][0], al[mt][1], al[mt][2], al[mt][3],
                             bh[nt][0], bh[nt][1]);
                }
        }
        __syncthreads();
    }

    // epilogue: bias + relu -> fp32 activations
#pragma unroll
    for (int mt = 0; mt < 4; mt++) {
#pragma unroll
        for (int nt = 0; nt < 4; nt++) {
            int col = col0 + nbase + nt * 8 + tig * 2;
            float bx = bias[col], by = bias[col + 1];
            int r0 = row0 + mbase + mt * 16 + gid;
            if (r0 < Nrows) {
                float2 o;
                o.x = fmaxf(acc[mt][nt][0] + bx, 0.f);
                o.y = fmaxf(acc[mt][nt][1] + by, 0.f);
                *(float2*)&out[(size_t)r0 * C + col] = o;
            }
            int r1 = r0 + 8;
            if (r1 < Nrows) {
                float2 o;
                o.x = fmaxf(acc[mt][nt][2] + bx, 0.f);
                o.y = fmaxf(acc[mt][nt][3] + by, 0.f);
                *(float2*)&out[(size_t)r1 * C + col] = o;
            }
        }
    }
}

// ---------------------------------------------------------------------------
__global__ __launch_bounds__(128) void k_pool() {
    int g = blockIdx.x;
    int c = blockIdx.y * 128 + threadIdx.x;
    int n0 = g_bnd[g];
    int n1 = g_bnd[g + 1];
    float acc = 0.f;
    for (int n = n0; n < n1; n++) acc += g_bufA[(size_t)n * 512 + c];
    float cntf = (float)(n1 - n0);
    g_pooled[g * 512 + c] = acc / fmaxf(cntf, 1.f);
}

// ---------------------------------------------------------------------------
__global__ __launch_bounds__(256) void k_dense(int in_sel,
                                               const float* __restrict__ W,
                                               const float* __restrict__ ba,
                                               const float* __restrict__ bb,
                                               float* out_ext, int In, int Out) {
    __shared__ __align__(16) float sin[512];
    const float* in = in_sel ? g_hl : g_pooled;
    float* out = out_ext ? out_ext : g_gates;
    int g = blockIdx.y;
    for (int k = threadIdx.x; k < In; k += blockDim.x) sin[k] = in[(size_t)g * In + k];
    __syncthreads();
    int j = blockIdx.x * blockDim.x + threadIdx.x;
    if (j >= Out) return;
    float acc = ba[j] + (bb ? bb[j] : 0.f);
    const float4* Wr = (const float4*)(W + (size_t)j * In);
    const float4* xs = (const float4*)sin;
    int k4 = In >> 2;
    for (int k = 0; k < k4; k++) {
        float4 w = Wr[k];
        float4 x = xs[k];
        acc += w.x * x.x + w.y * x.y + w.z * x.z + w.w * x.w;
    }
    out[(size_t)g * Out + j] = acc;
}

// h0=c0=0:  h = sigmoid(o) * tanh( sigmoid(i) * tanh(g) )
__global__ void k_lstm(int total, int H) {
    int i = blockIdx.x * blockDim.x + threadIdx.x;
    if (i >= total) return;
    int g = i / H;
    int j = i - g * H;
    const float* gr = g_gates + (size_t)g * 4 * H;
    float ii = gr[j];
    float gg = gr[2 * H + j];
    float oo = gr[3 * H + j];
    float si = 1.f / (1.f + expf(-ii));
    float so = 1.f / (1.f + expf(-oo));
    float c = si * tanhf(gg);
    g_hl[i] = so * tanhf(c);
}

// ---------------------------------------------------------------------------
extern "C" void kernel_launch(void* const* d_in, const int* in_sizes, int n_in,
                              void* d_out, int out_size) {
    const float* x     = (const float*)d_in[0];
    const void*  ei    = d_in[1];
    const void*  batch = d_in[2];
    const float *W1 = (const float*)d_in[3],  *b1 = (const float*)d_in[4];
    const float *W2 = (const float*)d_in[5],  *b2 = (const float*)d_in[6];
    const float *W3 = (const float*)d_in[7],  *b3 = (const float*)d_in[8];
    const float *Wih0 = (const float*)d_in[9];
    const float *bih0 = (const float*)d_in[11], *bhh0 = (const float*)d_in[12];
    const float *Wih1 = (const float*)d_in[13];
    const float *bih1 = (const float*)d_in[15], *bhh1 = (const float*)d_in[16];
    const float *Wp = (const float*)d_in[17],  *bp = (const float*)d_in[18];
    // Whh0 (d_in[10]) / Whh1 (d_in[14]) are dead: h0 = 0.

    int N = in_sizes[0] / 32;
    int E = in_sizes[1] / 2;
    int G = out_size / 512;

    const int T = 256;

    // ---- setup: dtype sniff + CSR build + norms + graph bounds ----
    k_detect_zero<<<cdiv(N, T), T>>>((const int*)ei, in_sizes[1],
                                     (const int*)batch, in_sizes[2], N);
    k_count<<<cdiv(E, T), T>>>(ei, E, N);
    k_prep<<<1, 1024>>>(batch, N, G);
    k_place<<<cdiv(E, T), T>>>(ei, E, N);

    // ---- GCN layer 1: agg(x)[N,32] -> relu(@W1+b1)[N,128] ----
    k_wsplit<<<cdiv(16 * 128, T), T>>>(W1, 32, 128);
    k_agg<<<cdiv(N * 8, T), T>>>(0, x, N * 8, 3);
    k_gemm_bf16<<<dim3(1, cdiv(N, 128)), 256>>>(b1, N, 32, 128);

    // ---- GCN layer 2: agg[N,128] -> relu(@W2+b2)[N,256] ----
    k_wsplit<<<cdiv(64 * 256, T), T>>>(W2, 128, 256);
    k_agg<<<cdiv(N * 32, T), T>>>(1, nullptr, N * 32, 5);
    k_gemm_bf16<<<dim3(2, cdiv(N, 128)), 256>>>(b2, N, 128, 256);

    // ---- GCN layer 3: agg[N,256] -> relu(@W3+b3)[N,512] ----
    k_wsplit<<<cdiv(128 * 512, T), T>>>(W3, 256, 512);
    k_agg<<<cdiv(N * 64, T), T>>>(1, nullptr, N * 64, 6);
    k_gemm_bf16<<<dim3(4, cdiv(N, 128)), 256>>>(b3, N, 256, 512);

    // ---- mean pool per graph ----
    k_pool<<<dim3(G, 4), 128>>>();

    // ---- LSTM (degenerate) + projection ----
    k_dense<<<dim3(4, G), 256>>>(0, Wih0, bih0, bhh0, nullptr, 512, 1024);
    k_lstm<<<cdiv(G * 256, T), T>>>(G * 256, 256);
    k_dense<<<dim3(4, G), 256>>>(1, Wih1, bih1, bhh1, nullptr, 256, 1024);
    k_lstm<<<cdiv(G * 256, T), T>>>(G * 256, 256);
    k_dense<<<dim3(2, G), 256>>>(1, Wp, bp, nullptr, (float*)d_out, 256, 512);
}